// round 4
// baseline (speedup 1.0000x reference)
#include <cuda_runtime.h>
#include <math.h>

// Problem constants
#define N_HALF 4096
#define N2     8192          // 2N rows
#define D      256           // feature dim
#define EPSN   1e-8f

// GEMM tiling
#define BM 64
#define BN 64
#define KC 64                // k-chunk
#define NKC (D / KC)         // 4
#define NJT (N2 / BN)        // 128 column tiles
#define THREADS 256          // 16 x 16

typedef unsigned long long ull;

// Scratch (device globals: allocation-free per harness rules)
__device__ float g_zn[N2 * D];     // normalized rows (8 MB, L2-resident)
__device__ float g_lse[N2];        // per-row logsumexp of logits (diag excluded)
__device__ float g_tgt[N2];        // per-row target logit
__device__ int   g_arg[N2];        // per-row argmax column

// ---------------- packed fp32x2 helpers (FFMA2) ----------------
__device__ __forceinline__ void ffma2(ull &c, ull a, ull b) {
    asm("fma.rn.f32x2 %0, %1, %2, %0;" : "+l"(c) : "l"(a), "l"(b));
}
__device__ __forceinline__ ull pack_dup(float x) {
    ull r; asm("mov.b64 %0, {%1, %1};" : "=l"(r) : "f"(x)); return r;
}
__device__ __forceinline__ void unpack2(ull v, float &lo, float &hi) {
    asm("mov.b64 {%0, %1}, %2;" : "=f"(lo), "=f"(hi) : "l"(v));
}

// ---------------- kernel 1: row normalization ----------------
// One warp per row. grid = N2/8 blocks of 256 threads.
__global__ void normalize_kernel(const float* __restrict__ z1,
                                 const float* __restrict__ z2) {
    int row  = blockIdx.x * 8 + (threadIdx.x >> 5);
    int lane = threadIdx.x & 31;
    const float* src = (row < N_HALF) ? (z1 + (size_t)row * D)
                                      : (z2 + (size_t)(row - N_HALF) * D);
    // each lane handles 8 contiguous floats
    float4 a = *reinterpret_cast<const float4*>(src + lane * 8);
    float4 b = *reinterpret_cast<const float4*>(src + lane * 8 + 4);
    float s = a.x*a.x + a.y*a.y + a.z*a.z + a.w*a.w
            + b.x*b.x + b.y*b.y + b.z*b.z + b.w*b.w;
    #pragma unroll
    for (int off = 16; off > 0; off >>= 1)
        s += __shfl_xor_sync(0xffffffffu, s, off);
    float nrm = sqrtf(s);
    float sc  = 1.0f / fmaxf(nrm, EPSN);
    float* dst = g_zn + (size_t)row * D;
    a.x*=sc; a.y*=sc; a.z*=sc; a.w*=sc;
    b.x*=sc; b.y*=sc; b.z*=sc; b.w*=sc;
    *reinterpret_cast<float4*>(dst + lane * 8)     = a;
    *reinterpret_cast<float4*>(dst + lane * 8 + 4) = b;
}

// ---------------- kernel 2: fused GEMM + online softmax/argmax ----------------
// grid = 128 CTAs (one 64-row block each), 256 threads (16x16), 4x4 microtile.
// Dynamic smem: As[256][64] (A panel, whole K) + Bs[2][64][64] (double-buffered).
#define SMEM_BYTES ((D * BM + 2 * KC * BN) * (int)sizeof(float))

__global__ void __launch_bounds__(THREADS, 1)
sim_softmax_kernel(const float* __restrict__ lt) {
    extern __shared__ float smem[];
    float (*As)[BM]      = reinterpret_cast<float (*)[BM]>(smem);
    float (*Bs)[KC][BN]  = reinterpret_cast<float (*)[KC][BN]>(smem + D * BM);

    const int tid  = threadIdx.x;
    const int tx   = tid & 15;         // column group
    const int ty   = tid >> 4;         // row group
    const int tx4  = tx * 4;
    const int ty4  = ty * 4;
    const int rBase = blockIdx.x * BM;

    const float invT = 1.0f / expf(lt[0]);

    // ---- load A panel (64 rows x 256 k), transposed into As[k][m] ----
    {
        int m  = tid >> 2;             // 0..63
        int ks = (tid & 3) * 64;       // 0,64,128,192
        const float* arow = g_zn + (size_t)(rBase + m) * D + ks;
        #pragma unroll
        for (int q = 0; q < 16; q++) {
            float4 v = *reinterpret_cast<const float4*>(arow + q * 4);
            As[ks + q*4 + 0][m] = v.x;
            As[ks + q*4 + 1][m] = v.y;
            As[ks + q*4 + 2][m] = v.z;
            As[ks + q*4 + 3][m] = v.w;
        }
    }
    __syncthreads();

    // per-thread online softmax / argmax state (4 rows each)
    float vmax[4], rsum[4];
    int   imax[4];
    #pragma unroll
    for (int i = 0; i < 4; i++) {
        vmax[i] = __int_as_float(0xff800000u);  // -inf
        rsum[i] = 0.0f;
        imax[i] = 0;
    }

    const int bn  = tid >> 2;          // 0..63 : B row within tile
    const int bks = (tid & 3) * 16;    // k segment within chunk

    for (int jt = 0; jt < NJT; jt++) {
        const int jBase = jt * BN;
        ull c[4][2] = {};              // 4 rows x 2 fp32x2 col-pairs

        // prefetch + store chunk 0
        {
            const float* src = g_zn + (size_t)(jBase + bn) * D + bks;
            float4 rb[4];
            #pragma unroll
            for (int q = 0; q < 4; q++)
                rb[q] = *reinterpret_cast<const float4*>(src + q * 4);
            #pragma unroll
            for (int q = 0; q < 4; q++) {
                Bs[0][bks + q*4 + 0][bn] = rb[q].x;
                Bs[0][bks + q*4 + 1][bn] = rb[q].y;
                Bs[0][bks + q*4 + 2][bn] = rb[q].z;
                Bs[0][bks + q*4 + 3][bn] = rb[q].w;
            }
        }
        __syncthreads();

        #pragma unroll
        for (int kc = 0; kc < NKC; kc++) {
            const int cur = kc & 1;
            float4 rbn[4];
            if (kc < NKC - 1) {        // prefetch next chunk (overlaps compute)
                const float* src = g_zn + (size_t)(jBase + bn) * D + (kc + 1) * KC + bks;
                #pragma unroll
                for (int q = 0; q < 4; q++)
                    rbn[q] = *reinterpret_cast<const float4*>(src + q * 4);
            }

            const float (*B)[BN] = Bs[cur];
            #pragma unroll 16
            for (int k = 0; k < KC; k++) {
                float4 av = *reinterpret_cast<const float4*>(&As[kc * KC + k][ty4]);
                ulonglong2 bv = *reinterpret_cast<const ulonglong2*>(&B[k][tx4]);
                ull a0 = pack_dup(av.x);
                ull a1 = pack_dup(av.y);
                ull a2 = pack_dup(av.z);
                ull a3 = pack_dup(av.w);
                ffma2(c[0][0], a0, bv.x); ffma2(c[0][1], a0, bv.y);
                ffma2(c[1][0], a1, bv.x); ffma2(c[1][1], a1, bv.y);
                ffma2(c[2][0], a2, bv.x); ffma2(c[2][1], a2, bv.y);
                ffma2(c[3][0], a3, bv.x); ffma2(c[3][1], a3, bv.y);
            }

            if (kc < NKC - 1) {
                const int nxt = cur ^ 1;
                #pragma unroll
                for (int q = 0; q < 4; q++) {
                    Bs[nxt][bks + q*4 + 0][bn] = rbn[q].x;
                    Bs[nxt][bks + q*4 + 1][bn] = rbn[q].y;
                    Bs[nxt][bks + q*4 + 2][bn] = rbn[q].z;
                    Bs[nxt][bks + q*4 + 3][bn] = rbn[q].w;
                }
            }
            __syncthreads();
        }

        // ---- epilogue: online update on this 4x4 sim block ----
        #pragma unroll
        for (int i = 0; i < 4; i++) {
            const int gi  = rBase + ty4 + i;
            const int tgt = (gi + N_HALF) & (N2 - 1);
            #pragma unroll
            for (int p = 0; p < 2; p++) {
                float s0, s1;
                unpack2(c[i][p], s0, s1);
                const int j0 = jBase + tx4 + 2 * p;
                #pragma unroll
                for (int e = 0; e < 2; e++) {
                    const float v = ((e == 0) ? s0 : s1) * invT;
                    const int   j = j0 + e;
                    if (j == tgt) g_tgt[gi] = v;
                    if (j != gi) {
                        if (v > vmax[i]) {
                            rsum[i] = rsum[i] * __expf(vmax[i] - v) + 1.0f;
                            vmax[i] = v;
                            imax[i] = j;
                        } else {
                            rsum[i] += __expf(v - vmax[i]);
                        }
                    }
                }
            }
        }
    }

    // ---- merge the 16 tx-lanes of each row via shfl.xor ----
    #pragma unroll
    for (int off = 1; off < 16; off <<= 1) {
        #pragma unroll
        for (int i = 0; i < 4; i++) {
            float vo = __shfl_xor_sync(0xffffffffu, vmax[i], off);
            float so = __shfl_xor_sync(0xffffffffu, rsum[i], off);
            int   io = __shfl_xor_sync(0xffffffffu, imax[i], off);
            float M  = fmaxf(vmax[i], vo);
            float r  = rsum[i] * __expf(vmax[i] - M) + so * __expf(vo - M);
            int   id = (vmax[i] > vo) ? imax[i]
                     : ((vo > vmax[i]) ? io : min(imax[i], io));
            vmax[i] = M; rsum[i] = r; imax[i] = id;
        }
    }
    if (tx == 0) {
        #pragma unroll
        for (int i = 0; i < 4; i++) {
            const int gi = rBase + ty4 + i;
            g_lse[gi] = vmax[i] + logf(rsum[i]);
            g_arg[gi] = imax[i];
        }
    }
}

// ---------------- kernel 3: final reduction ----------------
__global__ void finalize_kernel(float* __restrict__ out) {
    __shared__ float sl[THREADS];
    __shared__ int   sc[THREADS];
    const int tid = threadIdx.x;
    float lacc = 0.0f;
    int   cacc = 0;
    for (int i = tid; i < N2; i += THREADS) {
        const int tgt = (i + N_HALF) & (N2 - 1);
        lacc += g_lse[i] - g_tgt[i];      // -(target_logit - lse)
        cacc += (g_arg[i] == tgt) ? 1 : 0;
    }
    sl[tid] = lacc; sc[tid] = cacc;
    __syncthreads();
    for (int s = THREADS / 2; s > 0; s >>= 1) {
        if (tid < s) { sl[tid] += sl[tid + s]; sc[tid] += sc[tid + s]; }
        __syncthreads();
    }
    if (tid == 0) {
        out[0] = sl[0] / (float)N2;       // loss
        out[1] = 0.5f * (float)sc[0];     // correct
    }
}

extern "C" void kernel_launch(void* const* d_in, const int* in_sizes, int n_in,
                              void* d_out, int out_size) {
    const float* z1 = (const float*)d_in[0];
    const float* z2 = (const float*)d_in[1];
    const float* lt = (const float*)d_in[2];
    float* out = (float*)d_out;

    cudaFuncSetAttribute(sim_softmax_kernel,
                         cudaFuncAttributeMaxDynamicSharedMemorySize, SMEM_BYTES);

    normalize_kernel<<<N2 / 8, THREADS>>>(z1, z2);
    sim_softmax_kernel<<<N2 / BM, THREADS, SMEM_BYTES>>>(lt);
    finalize_kernel<<<1, THREADS>>>(out);
}

// round 5
// speedup vs baseline: 1.6739x; 1.6739x over previous
#include <cuda_runtime.h>
#include <math.h>

// Problem constants
#define N_HALF 4096
#define N2     8192          // 2N rows
#define D      256           // feature dim
#define EPSN   1e-8f

// GEMM tiling
#define BM 64
#define BN 64
#define KC 64                // k-chunk
#define NKC (D / KC)         // 4
#define NJT (N2 / BN)        // 128 column tiles
#define THREADS 256          // 16 x 16

typedef unsigned long long ull;

// Scratch (device globals: allocation-free per harness rules)
__device__ float g_zn[N2 * D];     // normalized rows (8 MB, L2-resident)
__device__ float g_lse[N2];        // per-row logsumexp of logits (diag excluded)
__device__ float g_tgt[N2];        // per-row target logit
__device__ int   g_arg[N2];        // per-row argmax column

// ---------------- packed fp32x2 helpers (FFMA2) ----------------
__device__ __forceinline__ void ffma2(ull &c, ull a, ull b) {
    asm("fma.rn.f32x2 %0, %1, %2, %0;" : "+l"(c) : "l"(a), "l"(b));
}
__device__ __forceinline__ ull pack_dup(float x) {
    ull r; asm("mov.b64 %0, {%1, %1};" : "=l"(r) : "f"(x)); return r;
}
__device__ __forceinline__ void unpack2(ull v, float &lo, float &hi) {
    asm("mov.b64 {%0, %1}, %2;" : "=f"(lo), "=f"(hi) : "l"(v));
}

// ---------------- kernel 1: row normalization ----------------
// One warp per row. grid = N2/8 blocks of 256 threads.
__global__ void normalize_kernel(const float* __restrict__ z1,
                                 const float* __restrict__ z2) {
    int row  = blockIdx.x * 8 + (threadIdx.x >> 5);
    int lane = threadIdx.x & 31;
    const float* src = (row < N_HALF) ? (z1 + (size_t)row * D)
                                      : (z2 + (size_t)(row - N_HALF) * D);
    // each lane handles 8 contiguous floats
    float4 a = *reinterpret_cast<const float4*>(src + lane * 8);
    float4 b = *reinterpret_cast<const float4*>(src + lane * 8 + 4);
    float s = a.x*a.x + a.y*a.y + a.z*a.z + a.w*a.w
            + b.x*b.x + b.y*b.y + b.z*b.z + b.w*b.w;
    #pragma unroll
    for (int off = 16; off > 0; off >>= 1)
        s += __shfl_xor_sync(0xffffffffu, s, off);
    float nrm = sqrtf(s);
    float sc  = 1.0f / fmaxf(nrm, EPSN);
    float* dst = g_zn + (size_t)row * D;
    a.x*=sc; a.y*=sc; a.z*=sc; a.w*=sc;
    b.x*=sc; b.y*=sc; b.z*=sc; b.w*=sc;
    *reinterpret_cast<float4*>(dst + lane * 8)     = a;
    *reinterpret_cast<float4*>(dst + lane * 8 + 4) = b;
}

// ---------------- kernel 2: fused GEMM + online softmax/argmax ----------------
// grid = 128 CTAs (one 64-row block each), 256 threads (16x16), 4x4 microtile.
// Dynamic smem: As[256][64] (A panel, whole K) + Bs[2][64][64] (double-buffered).
#define SMEM_BYTES ((D * BM + 2 * KC * BN) * (int)sizeof(float))

__global__ void __launch_bounds__(THREADS, 1)
sim_softmax_kernel(const float* __restrict__ lt) {
    extern __shared__ float smem[];
    float (*As)[BM]      = reinterpret_cast<float (*)[BM]>(smem);
    float (*Bs)[KC][BN]  = reinterpret_cast<float (*)[KC][BN]>(smem + D * BM);

    const int tid  = threadIdx.x;
    const int tx   = tid & 15;         // column group
    const int ty   = tid >> 4;         // row group
    const int tx4  = tx * 4;
    const int ty4  = ty * 4;
    const int rBase = blockIdx.x * BM;

    const float invT = 1.0f / expf(lt[0]);

    // ---- load A panel (64 rows x 256 k), transposed into As[k][m] ----
    {
        int m  = tid >> 2;             // 0..63
        int ks = (tid & 3) * 64;       // 0,64,128,192
        const float* arow = g_zn + (size_t)(rBase + m) * D + ks;
        #pragma unroll
        for (int q = 0; q < 16; q++) {
            float4 v = *reinterpret_cast<const float4*>(arow + q * 4);
            As[ks + q*4 + 0][m] = v.x;
            As[ks + q*4 + 1][m] = v.y;
            As[ks + q*4 + 2][m] = v.z;
            As[ks + q*4 + 3][m] = v.w;
        }
    }
    __syncthreads();

    // per-thread online softmax / argmax state (4 rows each)
    float vmax[4], rsum[4];
    int   imax[4];
    #pragma unroll
    for (int i = 0; i < 4; i++) {
        vmax[i] = __int_as_float(0xff800000u);  // -inf
        rsum[i] = 0.0f;
        imax[i] = 0;
    }

    const int bn  = tid >> 2;          // 0..63 : B row within tile
    const int bks = (tid & 3) * 16;    // k segment within chunk

    for (int jt = 0; jt < NJT; jt++) {
        const int jBase = jt * BN;
        ull c[4][2] = {};              // 4 rows x 2 fp32x2 col-pairs

        // prefetch + store chunk 0
        {
            const float* src = g_zn + (size_t)(jBase + bn) * D + bks;
            float4 rb[4];
            #pragma unroll
            for (int q = 0; q < 4; q++)
                rb[q] = *reinterpret_cast<const float4*>(src + q * 4);
            #pragma unroll
            for (int q = 0; q < 4; q++) {
                Bs[0][bks + q*4 + 0][bn] = rb[q].x;
                Bs[0][bks + q*4 + 1][bn] = rb[q].y;
                Bs[0][bks + q*4 + 2][bn] = rb[q].z;
                Bs[0][bks + q*4 + 3][bn] = rb[q].w;
            }
        }
        __syncthreads();

        #pragma unroll
        for (int kc = 0; kc < NKC; kc++) {
            const int cur = kc & 1;
            float4 rbn[4];
            if (kc < NKC - 1) {        // prefetch next chunk (overlaps compute)
                const float* src = g_zn + (size_t)(jBase + bn) * D + (kc + 1) * KC + bks;
                #pragma unroll
                for (int q = 0; q < 4; q++)
                    rbn[q] = *reinterpret_cast<const float4*>(src + q * 4);
            }

            const float (*B)[BN] = Bs[cur];
            #pragma unroll 16
            for (int k = 0; k < KC; k++) {
                float4 av = *reinterpret_cast<const float4*>(&As[kc * KC + k][ty4]);
                ulonglong2 bv = *reinterpret_cast<const ulonglong2*>(&B[k][tx4]);
                ull a0 = pack_dup(av.x);
                ull a1 = pack_dup(av.y);
                ull a2 = pack_dup(av.z);
                ull a3 = pack_dup(av.w);
                ffma2(c[0][0], a0, bv.x); ffma2(c[0][1], a0, bv.y);
                ffma2(c[1][0], a1, bv.x); ffma2(c[1][1], a1, bv.y);
                ffma2(c[2][0], a2, bv.x); ffma2(c[2][1], a2, bv.y);
                ffma2(c[3][0], a3, bv.x); ffma2(c[3][1], a3, bv.y);
            }

            if (kc < NKC - 1) {
                const int nxt = cur ^ 1;
                #pragma unroll
                for (int q = 0; q < 4; q++) {
                    Bs[nxt][bks + q*4 + 0][bn] = rbn[q].x;
                    Bs[nxt][bks + q*4 + 1][bn] = rbn[q].y;
                    Bs[nxt][bks + q*4 + 2][bn] = rbn[q].z;
                    Bs[nxt][bks + q*4 + 3][bn] = rbn[q].w;
                }
            }
            __syncthreads();
        }

        // ---- epilogue: online update on this 4x4 sim block ----
        #pragma unroll
        for (int i = 0; i < 4; i++) {
            const int gi  = rBase + ty4 + i;
            const int tgt = (gi + N_HALF) & (N2 - 1);
            #pragma unroll
            for (int p = 0; p < 2; p++) {
                float s0, s1;
                unpack2(c[i][p], s0, s1);
                const int j0 = jBase + tx4 + 2 * p;
                #pragma unroll
                for (int e = 0; e < 2; e++) {
                    const float v = ((e == 0) ? s0 : s1) * invT;
                    const int   j = j0 + e;
                    if (j == tgt) g_tgt[gi] = v;
                    if (j != gi) {
                        if (v > vmax[i]) {
                            rsum[i] = rsum[i] * __expf(vmax[i] - v) + 1.0f;
                            vmax[i] = v;
                            imax[i] = j;
                        } else {
                            rsum[i] += __expf(v - vmax[i]);
                        }
                    }
                }
            }
        }
    }

    // ---- merge the 16 tx-lanes of each row via shfl.xor ----
    #pragma unroll
    for (int off = 1; off < 16; off <<= 1) {
        #pragma unroll
        for (int i = 0; i < 4; i++) {
            float vo = __shfl_xor_sync(0xffffffffu, vmax[i], off);
            float so = __shfl_xor_sync(0xffffffffu, rsum[i], off);
            int   io = __shfl_xor_sync(0xffffffffu, imax[i], off);
            float M  = fmaxf(vmax[i], vo);
            float r  = rsum[i] * __expf(vmax[i] - M) + so * __expf(vo - M);
            int   id = (vmax[i] > vo) ? imax[i]
                     : ((vo > vmax[i]) ? io : min(imax[i], io));
            vmax[i] = M; rsum[i] = r; imax[i] = id;
        }
    }
    if (tx == 0) {
        #pragma unroll
        for (int i = 0; i < 4; i++) {
            const int gi = rBase + ty4 + i;
            g_lse[gi] = vmax[i] + logf(rsum[i]);
            g_arg[gi] = imax[i];
        }
    }
}

// ---------------- kernel 3: final reduction ----------------
__global__ void finalize_kernel(float* __restrict__ out) {
    __shared__ float sl[THREADS];
    __shared__ int   sc[THREADS];
    const int tid = threadIdx.x;
    float lacc = 0.0f;
    int   cacc = 0;
    for (int i = tid; i < N2; i += THREADS) {
        const int tgt = (i + N_HALF) & (N2 - 1);
        lacc += g_lse[i] - g_tgt[i];      // -(target_logit - lse)
        cacc += (g_arg[i] == tgt) ? 1 : 0;
    }
    sl[tid] = lacc; sc[tid] = cacc;
    __syncthreads();
    for (int s = THREADS / 2; s > 0; s >>= 1) {
        if (tid < s) { sl[tid] += sl[tid + s]; sc[tid] += sc[tid + s]; }
        __syncthreads();
    }
    if (tid == 0) {
        out[0] = sl[0] / (float)N2;       // loss
        out[1] = 0.5f * (float)sc[0];     // correct
    }
}

extern "C" void kernel_launch(void* const* d_in, const int* in_sizes, int n_in,
                              void* d_out, int out_size) {
    const float* z1 = (const float*)d_in[0];
    const float* z2 = (const float*)d_in[1];
    const float* lt = (const float*)d_in[2];
    float* out = (float*)d_out;

    cudaFuncSetAttribute(sim_softmax_kernel,
                         cudaFuncAttributeMaxDynamicSharedMemorySize, SMEM_BYTES);

    normalize_kernel<<<N2 / 8, THREADS>>>(z1, z2);
    sim_softmax_kernel<<<N2 / BM, THREADS, SMEM_BYTES>>>(lt);
    finalize_kernel<<<1, THREADS>>>(out);
}

// round 7
// speedup vs baseline: 5.8612x; 3.5015x over previous
#include <cuda_runtime.h>
#include <cuda_bf16.h>
#include <math.h>
#include <stdint.h>

// ---------------- problem constants ----------------
#define N_HALF 4096
#define N2     8192
#define Dm     256
#define EPSN   1e-8f

// ---------------- device scratch ----------------
__device__ __align__(16) __nv_bfloat16 gH[N2 * Dm];   // hi part, row-major
__device__ __align__(16) __nv_bfloat16 gL[N2 * Dm];   // lo part, row-major
__device__ float g_pf [32][N2];    // partial expsum (fixed C)
__device__ float g_pmv[32][N2];    // partial max sim
__device__ int   g_pmc[32][N2];    // partial argmax col
__device__ float g_tgt[N2];        // target logit per row
__device__ float g_redl[32];
__device__ int   g_redc[32];

// ---------------- PTX helpers (all sm_80-era: compile under compute_103) ----
__device__ __forceinline__ uint32_t smem_u32(const void* p) {
    uint32_t a;
    asm("{ .reg .u64 t; cvta.to.shared.u64 t, %1; cvt.u32.u64 %0, t; }" : "=r"(a) : "l"(p));
    return a;
}
__device__ __forceinline__ void cp16(uint32_t sdst, const void* gsrc) {
    asm volatile("cp.async.cg.shared.global [%0], [%1], 16;" :: "r"(sdst), "l"(gsrc) : "memory");
}
__device__ __forceinline__ void cp_commit() {
    asm volatile("cp.async.commit_group;" ::: "memory");
}
__device__ __forceinline__ void cp_wait1() {
    asm volatile("cp.async.wait_group 1;" ::: "memory");
}
__device__ __forceinline__ void ldm_x4(uint32_t* r, uint32_t addr) {
    asm volatile("ldmatrix.sync.aligned.m8n8.x4.shared.b16 {%0,%1,%2,%3}, [%4];"
        : "=r"(r[0]), "=r"(r[1]), "=r"(r[2]), "=r"(r[3]) : "r"(addr));
}
__device__ __forceinline__ void mma16816(float* d, const uint32_t* a, uint32_t b0, uint32_t b1) {
    asm volatile("mma.sync.aligned.m16n8k16.row.col.f32.bf16.bf16.f32 "
        "{%0,%1,%2,%3}, {%4,%5,%6,%7}, {%8,%9}, {%0,%1,%2,%3};"
        : "+f"(d[0]), "+f"(d[1]), "+f"(d[2]), "+f"(d[3])
        : "r"(a[0]), "r"(a[1]), "r"(a[2]), "r"(a[3]), "r"(b0), "r"(b1));
}

// smem map (offsets from 1024-aligned base)
#define SM_AH   0u          // 128 x 256 bf16 = 64KB  (512B rows, swizzled)
#define SM_AL   65536u
#define SM_B    131072u     // 2 stages x 16KB (128 x 64 bf16, 128B rows, swizzled)
#define SMEM_BYTES (131072 + 32768 + 1024)

// ---------------- kernel 1: normalize + bf16 hi/lo split ----------------
__global__ void normalize_kernel(const float* __restrict__ z1,
                                 const float* __restrict__ z2) {
    int row  = blockIdx.x * 8 + (threadIdx.x >> 5);
    int lane = threadIdx.x & 31;
    const float* src = (row < N_HALF) ? (z1 + (size_t)row * Dm)
                                      : (z2 + (size_t)(row - N_HALF) * Dm);
    float4 a = *reinterpret_cast<const float4*>(src + lane * 8);
    float4 b = *reinterpret_cast<const float4*>(src + lane * 8 + 4);
    float s = a.x*a.x + a.y*a.y + a.z*a.z + a.w*a.w
            + b.x*b.x + b.y*b.y + b.z*b.z + b.w*b.w;
    #pragma unroll
    for (int off = 16; off > 0; off >>= 1)
        s += __shfl_xor_sync(0xffffffffu, s, off);
    float sc = 1.0f / fmaxf(sqrtf(s), EPSN);
    float v[8] = {a.x*sc, a.y*sc, a.z*sc, a.w*sc, b.x*sc, b.y*sc, b.z*sc, b.w*sc};
    union { __nv_bfloat16 h[8]; uint4 u; } H, L;
    #pragma unroll
    for (int i = 0; i < 8; i++) {
        H.h[i] = __float2bfloat16(v[i]);
        L.h[i] = __float2bfloat16(v[i] - __bfloat162float(H.h[i]));
    }
    *reinterpret_cast<uint4*>((uint8_t*)gH + (size_t)row * 512 + lane * 16) = H.u;
    *reinterpret_cast<uint4*>((uint8_t*)gL + (size_t)row * 512 + lane * 16) = L.u;
}

// ---------------- kernel 2: fused HMMA split-GEMM + softmax/argmax ----------
// grid: 1024 CTAs = 64 mi x 16 ng.  CTA: rows [mi*128,+128) x cols [ng*512,+512)
// 8 warps: wm = wid&3 (32-row strip), wn = wid>>2 (64-col strip).
__global__ void __launch_bounds__(256, 1)
sim_hmma_kernel(const float* __restrict__ lt) {
    extern __shared__ char smraw[];
    uint32_t sb = smem_u32(smraw);
    sb = (sb + 1023u) & ~1023u;

    const int tid  = threadIdx.x;
    const int lane = tid & 31;
    const int wid  = tid >> 5;
    const int wm   = wid & 3;
    const int wn   = wid >> 2;
    const int mi   = blockIdx.x >> 4;
    const int ng   = blockIdx.x & 15;

    const float invT = expf(-lt[0]);         // 1/T
    const float Cc   = invT;                 // fixed softmax shift (max logit)

    // ---- A panels: hi + lo, 8192 x 16B units ----
    {
        int u = tid;
        #pragma unroll
        for (int i = 0; i < 32; i++, u += 256) {
            int panel = u >> 12, rr = (u >> 5) & 127, ku = u & 31;
            const uint8_t* g = panel ? (const uint8_t*)gL : (const uint8_t*)gH;
            const uint8_t* gsrc = g + ((size_t)(mi * 128 + rr)) * 512 + ku * 16;
            uint32_t sdst = (sb + panel * 65536u + rr * 512u + ku * 16u) ^ ((rr & 7) << 4);
            cp16(sdst, gsrc);
        }
        cp_commit();
    }

    // ---- B chunk loader ----
    auto loadB = [&](int q) {
        int jt = q >> 3, r = q & 7, c = r >> 1, st = q & 1;
        const uint8_t* g = (r & 1) ? (const uint8_t*)gL : (const uint8_t*)gH;
        int colbase = ng * 512 + jt * 128;
        int u = tid;
        #pragma unroll
        for (int i = 0; i < 4; i++, u += 256) {
            int rr = u >> 3, ku = u & 7;
            const uint8_t* gsrc = g + ((size_t)(colbase + rr)) * 512 + c * 128 + ku * 16;
            uint32_t sdst = (sb + SM_B + st * 16384u + rr * 128u + ku * 16u) ^ ((rr & 7) << 4);
            cp16(sdst, gsrc);
        }
    };
    loadB(0); cp_commit();
    loadB(1); cp_commit();

    // lane-constant address pieces
    const uint32_t a_lo = (lane & 15) * 512u + (lane >> 4) * 16u;
    const uint32_t b_lo = ((lane & 7) + ((lane >> 3) & 1) * 8) * 128u + (lane >> 4) * 16u;
    const uint32_t lxr  = (uint32_t)(lane & 7) << 4;
    const uint32_t AhB  = sb + SM_AH + wm * 16384u;   // + wm*32*512
    const uint32_t AlB  = sb + SM_AL + wm * 16384u;

    // epilogue state (4 row-slots per lane)
    const int rowA = mi * 128 + wm * 32 + (lane >> 2);
    int   gi_s[4];
    float fsum[4], mv[4];
    int   mc[4];
    #pragma unroll
    for (int s = 0; s < 4; s++) {
        gi_s[s] = rowA + s * 8;
        fsum[s] = 0.0f; mv[s] = -INFINITY; mc[s] = 0;
    }

    float acc[2][8][4];

    for (int q = 0; q < 32; q++) {
        const int jt = q >> 3, r = q & 7;
        if (r == 0) {
            #pragma unroll
            for (int mf = 0; mf < 2; mf++)
                #pragma unroll
                for (int nf = 0; nf < 8; nf++)
                    #pragma unroll
                    for (int v = 0; v < 4; v++) acc[mf][nf][v] = 0.0f;
        }

        cp_wait1();
        __syncthreads();

        // ---- compute chunk q ----
        {
            const int st = q & 1, c = r >> 1, kb = c * 64;
            const bool dual = ((r & 1) == 0);     // Bh chunk -> hh + lh
            const uint32_t Bst = sb + SM_B + st * 16384u + wn * 8192u;
            #pragma unroll
            for (int kk = 0; kk < 64; kk += 16) {
                uint32_t bfr[4][4];
                #pragma unroll
                for (int nb = 0; nb < 4; nb++)
                    ldm_x4(bfr[nb], (Bst + nb * 2048u + kk * 2u + b_lo) ^ lxr);
                uint32_t af[2][4];
                #pragma unroll
                for (int mf = 0; mf < 2; mf++)
                    ldm_x4(af[mf], (AhB + mf * 8192u + (kb + kk) * 2u + a_lo) ^ lxr);
                #pragma unroll
                for (int mf = 0; mf < 2; mf++)
                    #pragma unroll
                    for (int nb = 0; nb < 4; nb++) {
                        mma16816(acc[mf][nb*2  ], af[mf], bfr[nb][0], bfr[nb][2]);
                        mma16816(acc[mf][nb*2+1], af[mf], bfr[nb][1], bfr[nb][3]);
                    }
                if (dual) {
                    uint32_t al[2][4];
                    #pragma unroll
                    for (int mf = 0; mf < 2; mf++)
                        ldm_x4(al[mf], (AlB + mf * 8192u + (kb + kk) * 2u + a_lo) ^ lxr);
                    #pragma unroll
                    for (int mf = 0; mf < 2; mf++)
                        #pragma unroll
                        for (int nb = 0; nb < 4; nb++) {
                            mma16816(acc[mf][nb*2  ], al[mf], bfr[nb][0], bfr[nb][2]);
                            mma16816(acc[mf][nb*2+1], al[mf], bfr[nb][1], bfr[nb][3]);
                        }
                }
            }
        }

        __syncthreads();
        if (q + 2 < 32) loadB(q + 2);
        cp_commit();

        // ---- per-jt epilogue (registers only; overlaps next B loads) ----
        if (r == 7) {
            const bool diagJt = (ng == (mi >> 2))        && (jt == (mi & 3));
            const bool tgtJt  = (ng == ((mi >> 2) ^ 8))  && (jt == (mi & 3));
            const int jbase = ng * 512 + jt * 128 + wn * 64 + (lane & 3) * 2;
            #pragma unroll
            for (int mf = 0; mf < 2; mf++)
                #pragma unroll
                for (int nf = 0; nf < 8; nf++)
                    #pragma unroll
                    for (int v = 0; v < 4; v++) {
                        const int s  = mf * 2 + (v >> 1);
                        const int j  = jbase + nf * 8 + (v & 1);
                        const float sv = acc[mf][nf][v];
                        const float e  = __expf((sv - 1.0f) * invT);
                        if (tgtJt && j == (gi_s[s] ^ 4096))
                            g_tgt[gi_s[s]] = sv * invT;
                        if (!(diagJt && j == gi_s[s])) {
                            fsum[s] += e;
                            if (sv > mv[s]) { mv[s] = sv; mc[s] = j; }
                        }
                    }
        }
    }

    // ---- merge 4 lanes sharing each row, write partials ----
    const int slot = ng * 2 + wn;
    #pragma unroll
    for (int s = 0; s < 4; s++) {
        #pragma unroll
        for (int o = 1; o < 4; o <<= 1) {
            float of = __shfl_xor_sync(0xffffffffu, fsum[s], o);
            float ov = __shfl_xor_sync(0xffffffffu, mv[s],   o);
            int   oc = __shfl_xor_sync(0xffffffffu, mc[s],   o);
            fsum[s] += of;
            if (ov > mv[s] || (ov == mv[s] && oc < mc[s])) { mv[s] = ov; mc[s] = oc; }
        }
        if ((lane & 3) == 0) {
            g_pf [slot][gi_s[s]] = fsum[s];
            g_pmv[slot][gi_s[s]] = mv[s];
            g_pmc[slot][gi_s[s]] = mc[s];
        }
    }
    // gi_s[0]^4096 unused warning suppression: nothing
}

// ---------------- kernel 3a: per-row reduce over 32 slots ----------------
__global__ void finalizeA_kernel(const float* __restrict__ lt) {
    __shared__ float sl[256];
    __shared__ int   sc[256];
    const int tid = threadIdx.x;
    const int row = blockIdx.x * 256 + tid;
    const float invT = expf(-lt[0]);
    float fs = 0.0f, bv = -INFINITY;
    int bc = -1;
    #pragma unroll
    for (int s = 0; s < 32; s++) {
        fs += g_pf[s][row];
        float v = g_pmv[s][row];
        int   c = g_pmc[s][row];
        if (v > bv || (v == bv && c < bc)) { bv = v; bc = c; }
    }
    float lse = invT + logf(fs);
    sl[tid] = lse - g_tgt[row];
    sc[tid] = (bc == (row ^ 4096)) ? 1 : 0;
    __syncthreads();
    for (int s = 128; s > 0; s >>= 1) {
        if (tid < s) { sl[tid] += sl[tid + s]; sc[tid] += sc[tid + s]; }
        __syncthreads();
    }
    if (tid == 0) { g_redl[blockIdx.x] = sl[0]; g_redc[blockIdx.x] = sc[0]; }
}

// ---------------- kernel 3b: final scalar ----------------
__global__ void finalizeB_kernel(float* __restrict__ out) {
    const int tid = threadIdx.x;  // 32 threads
    float l = g_redl[tid];
    int   c = g_redc[tid];
    #pragma unroll
    for (int o = 16; o > 0; o >>= 1) {
        l += __shfl_xor_sync(0xffffffffu, l, o);
        c += __shfl_xor_sync(0xffffffffu, c, o);
    }
    if (tid == 0) {
        out[0] = l / (float)N2;
        out[1] = 0.5f * (float)c;
    }
}

extern "C" void kernel_launch(void* const* d_in, const int* in_sizes, int n_in,
                              void* d_out, int out_size) {
    const float* z1 = (const float*)d_in[0];
    const float* z2 = (const float*)d_in[1];
    const float* lt = (const float*)d_in[2];
    float* out = (float*)d_out;

    cudaFuncSetAttribute(sim_hmma_kernel,
                         cudaFuncAttributeMaxDynamicSharedMemorySize, SMEM_BYTES);

    normalize_kernel<<<N2 / 8, 256>>>(z1, z2);
    sim_hmma_kernel<<<1024, 256, SMEM_BYTES>>>(lt);
    finalizeA_kernel<<<32, 256>>>(lt);
    finalizeB_kernel<<<1, 32>>>(out);
}

// round 8
// speedup vs baseline: 8.8562x; 1.5110x over previous
#include <cuda_runtime.h>
#include <cuda_bf16.h>
#include <math.h>
#include <stdint.h>

// ---------------- problem constants ----------------
#define N_HALF 4096
#define N2     8192
#define Dm     256
#define EPSN   1e-8f
#define NBLK   64            // 8192 / 128 row blocks
#define NTILE  2080          // NBLK*(NBLK+1)/2 upper-tri tiles

// ---------------- device scratch ----------------
__device__ __align__(16) __nv_bfloat16 gH[N2 * Dm];   // hi part, row-major
__device__ __align__(16) __nv_bfloat16 gL[N2 * Dm];   // lo part, row-major
// partials: slot o = "other" block; each (o,row) written exactly once
__device__ float g_pf [NBLK][N2];   // partial expsum (fixed shift C = 1/T)
__device__ float g_pmv[NBLK][N2];   // partial max sim
__device__ int   g_pmc[NBLK][N2];   // partial argmax col (global)
__device__ float g_tgt[N2];         // target logit per row
__device__ float g_redl[32];
__device__ int   g_redc[32];

// ---------------- PTX helpers (sm_80-era: compile under compute_103) ------
__device__ __forceinline__ uint32_t smem_u32(const void* p) {
    uint32_t a;
    asm("{ .reg .u64 t; cvta.to.shared.u64 t, %1; cvt.u32.u64 %0, t; }" : "=r"(a) : "l"(p));
    return a;
}
__device__ __forceinline__ void cp16(uint32_t sdst, const void* gsrc) {
    asm volatile("cp.async.cg.shared.global [%0], [%1], 16;" :: "r"(sdst), "l"(gsrc) : "memory");
}
__device__ __forceinline__ void cp_commit() {
    asm volatile("cp.async.commit_group;" ::: "memory");
}
__device__ __forceinline__ void cp_wait1() {
    asm volatile("cp.async.wait_group 1;" ::: "memory");
}
__device__ __forceinline__ void ldm_x4(uint32_t* r, uint32_t addr) {
    asm volatile("ldmatrix.sync.aligned.m8n8.x4.shared.b16 {%0,%1,%2,%3}, [%4];"
        : "=r"(r[0]), "=r"(r[1]), "=r"(r[2]), "=r"(r[3]) : "r"(addr));
}
__device__ __forceinline__ void mma16816(float* d, const uint32_t* a, uint32_t b0, uint32_t b1) {
    asm volatile("mma.sync.aligned.m16n8k16.row.col.f32.bf16.bf16.f32 "
        "{%0,%1,%2,%3}, {%4,%5,%6,%7}, {%8,%9}, {%0,%1,%2,%3};"
        : "+f"(d[0]), "+f"(d[1]), "+f"(d[2]), "+f"(d[3])
        : "r"(a[0]), "r"(a[1]), "r"(a[2]), "r"(a[3]), "r"(b0), "r"(b1));
}

// smem map (offsets from 1024-aligned base)
#define SM_AH   0u          // 128 x 256 bf16 hi = 64KB (512B rows, swizzled)
#define SM_AL   65536u      // lo panel
#define SM_B    131072u     // 2 stages x 16KB (128 rows x 64 bf16, swizzled)
// epilogue reduction scratch (reuses B area after mainloop)
#define SM_RF   (SM_B + 0u)      // float[128] row expsum (wn=1)
#define SM_RV   (SM_B + 512u)    // float[128] row max
#define SM_RC   (SM_B + 1024u)   // int  [128] row argmax (col_local)
#define SM_CF   (SM_B + 2048u)   // float[4][128] col expsum per wm
#define SM_CV   (SM_B + 4096u)   // float[4][128]
#define SM_CC   (SM_B + 6144u)   // int  [4][128]
#define SMEM_BYTES (131072 + 32768 + 1024)

// ---------------- kernel 1: normalize + bf16 hi/lo split ----------------
__global__ void normalize_kernel(const float* __restrict__ z1,
                                 const float* __restrict__ z2) {
    int row  = blockIdx.x * 8 + (threadIdx.x >> 5);
    int lane = threadIdx.x & 31;
    const float* src = (row < N_HALF) ? (z1 + (size_t)row * Dm)
                                      : (z2 + (size_t)(row - N_HALF) * Dm);
    float4 a = *reinterpret_cast<const float4*>(src + lane * 8);
    float4 b = *reinterpret_cast<const float4*>(src + lane * 8 + 4);
    float s = a.x*a.x + a.y*a.y + a.z*a.z + a.w*a.w
            + b.x*b.x + b.y*b.y + b.z*b.z + b.w*b.w;
    #pragma unroll
    for (int off = 16; off > 0; off >>= 1)
        s += __shfl_xor_sync(0xffffffffu, s, off);
    float sc = 1.0f / fmaxf(sqrtf(s), EPSN);
    float v[8] = {a.x*sc, a.y*sc, a.z*sc, a.w*sc, b.x*sc, b.y*sc, b.z*sc, b.w*sc};
    union { __nv_bfloat16 h[8]; uint4 u; } H, L;
    #pragma unroll
    for (int i = 0; i < 8; i++) {
        H.h[i] = __float2bfloat16(v[i]);
        L.h[i] = __float2bfloat16(v[i] - __bfloat162float(H.h[i]));
    }
    *reinterpret_cast<uint4*>((uint8_t*)gH + (size_t)row * 512 + lane * 16) = H.u;
    *reinterpret_cast<uint4*>((uint8_t*)gL + (size_t)row * 512 + lane * 16) = L.u;
}

// ---------------- kernel 2: symmetric HMMA split-GEMM + dual-direction softmax
// grid: 2080 CTAs, one upper-triangle 128x128 tile (bi <= bj) each.
// 8 warps: wm = wid&3 (32-row strip), wn = wid>>2 (64-col strip).
__global__ void __launch_bounds__(256, 1)
sim_hmma_kernel(const float* __restrict__ lt) {
    extern __shared__ char smraw[];
    uint32_t sb = smem_u32(smraw);
    sb = (sb + 1023u) & ~1023u;

    const int tid  = threadIdx.x;
    const int lane = tid & 31;
    const int wid  = tid >> 5;
    const int wm   = wid & 3;
    const int wn   = wid >> 2;

    // tile (bi, bj) from triangular index
    int t = blockIdx.x;
    int bi = (int)((129.0 - sqrt(16641.0 - 8.0 * (double)t)) * 0.5);
    while (bi * (129 - bi) / 2 > t) bi--;
    while ((bi + 1) * (128 - bi) / 2 <= t) bi++;
    const int bj = bi + (t - bi * (129 - bi) / 2);

    const float invT = expf(-lt[0]);

    // ---- A panels (block bi): hi + lo, 8192 x 16B units ----
    {
        int u = tid;
        #pragma unroll
        for (int i = 0; i < 32; i++, u += 256) {
            int panel = u >> 12, rr = (u >> 5) & 127, ku = u & 31;
            const uint8_t* g = panel ? (const uint8_t*)gL : (const uint8_t*)gH;
            const uint8_t* gsrc = g + ((size_t)(bi * 128 + rr)) * 512 + ku * 16;
            uint32_t sdst = (sb + panel * 65536u + rr * 512u + ku * 16u) ^ ((rr & 7) << 4);
            cp16(sdst, gsrc);
        }
        cp_commit();
    }

    // ---- B chunk loader (block bj): q in [0,8): c=q>>1 (k-offset), q&1 -> lo
    auto loadB = [&](int q) {
        int c = q >> 1, st = q & 1;
        const uint8_t* g = (q & 1) ? (const uint8_t*)gL : (const uint8_t*)gH;
        int u = tid;
        #pragma unroll
        for (int i = 0; i < 4; i++, u += 256) {
            int rr = u >> 3, ku = u & 7;
            const uint8_t* gsrc = g + ((size_t)(bj * 128 + rr)) * 512 + c * 128 + ku * 16;
            uint32_t sdst = (sb + SM_B + st * 16384u + rr * 128u + ku * 16u) ^ ((rr & 7) << 4);
            cp16(sdst, gsrc);
        }
    };
    loadB(0); cp_commit();
    loadB(1); cp_commit();

    // lane-constant address pieces
    const uint32_t a_lo = (lane & 15) * 512u + (lane >> 4) * 16u;
    const uint32_t b_lo = ((lane & 7) + ((lane >> 3) & 1) * 8) * 128u + (lane >> 4) * 16u;
    const uint32_t lxr  = (uint32_t)(lane & 7) << 4;
    const uint32_t AhB  = sb + SM_AH + wm * 16384u;
    const uint32_t AlB  = sb + SM_AL + wm * 16384u;

    float acc[2][8][4];
    #pragma unroll
    for (int mf = 0; mf < 2; mf++)
        #pragma unroll
        for (int nf = 0; nf < 8; nf++)
            #pragma unroll
            for (int v = 0; v < 4; v++) acc[mf][nf][v] = 0.0f;

    for (int q = 0; q < 8; q++) {
        cp_wait1();
        __syncthreads();
        {
            const int st = q & 1, kb = (q >> 1) * 64;
            const bool dual = ((q & 1) == 0);      // Bh chunk -> hh + lh
            const uint32_t Bst = sb + SM_B + st * 16384u + wn * 8192u;
            #pragma unroll
            for (int kk = 0; kk < 64; kk += 16) {
                uint32_t bfr[4][4];
                #pragma unroll
                for (int nb = 0; nb < 4; nb++)
                    ldm_x4(bfr[nb], (Bst + nb * 2048u + kk * 2u + b_lo) ^ lxr);
                uint32_t af[2][4];
                #pragma unroll
                for (int mf = 0; mf < 2; mf++)
                    ldm_x4(af[mf], (AhB + mf * 8192u + (kb + kk) * 2u + a_lo) ^ lxr);
                #pragma unroll
                for (int mf = 0; mf < 2; mf++)
                    #pragma unroll
                    for (int nb = 0; nb < 4; nb++) {
                        mma16816(acc[mf][nb*2  ], af[mf], bfr[nb][0], bfr[nb][2]);
                        mma16816(acc[mf][nb*2+1], af[mf], bfr[nb][1], bfr[nb][3]);
                    }
                if (dual) {
                    uint32_t al[2][4];
                    #pragma unroll
                    for (int mf = 0; mf < 2; mf++)
                        ldm_x4(al[mf], (AlB + mf * 8192u + (kb + kk) * 2u + a_lo) ^ lxr);
                    #pragma unroll
                    for (int mf = 0; mf < 2; mf++)
                        #pragma unroll
                        for (int nb = 0; nb < 4; nb++) {
                            mma16816(acc[mf][nb*2  ], al[mf], bfr[nb][0], bfr[nb][2]);
                            mma16816(acc[mf][nb*2+1], al[mf], bfr[nb][1], bfr[nb][3]);
                        }
                }
            }
        }
        __syncthreads();
        if (q + 2 < 8) loadB(q + 2);
        cp_commit();
    }

    // ================= epilogue: dual-direction reduction =================
    const int  lq     = lane >> 2;
    const bool isDiag = (bi == bj);
    const bool isTgt  = (bj == bi + 32);

    float fsum[4], mv[4];  int mc[4];          // row direction (4 row slots)
    float csum[16], cv[16]; int cim[16];       // col direction (16 col slots)
    #pragma unroll
    for (int s = 0; s < 4; s++)  { fsum[s] = 0.0f; mv[s] = -INFINITY; mc[s] = 0; }
    #pragma unroll
    for (int c = 0; c < 16; c++) { csum[c] = 0.0f; cv[c] = -INFINITY; cim[c] = 0; }

    #pragma unroll
    for (int mf = 0; mf < 2; mf++)
        #pragma unroll
        for (int nf = 0; nf < 8; nf++)
            #pragma unroll
            for (int v = 0; v < 4; v++) {
                const int rl = wm * 32 + mf * 16 + lq + (v >> 1) * 8;
                const int cl = wn * 64 + (lane & 3) * 2 + nf * 8 + (v & 1);
                const float sv = acc[mf][nf][v];
                const float e  = __expf((sv - 1.0f) * invT);
                const bool same = (rl == cl);
                if (isTgt && same) {
                    const float tv = sv * invT;
                    g_tgt[bi * 128 + rl]        = tv;
                    g_tgt[bi * 128 + rl + 4096] = tv;
                }
                if (!(isDiag && same)) {
                    const int s = mf * 2 + (v >> 1), c = nf * 2 + (v & 1);
                    fsum[s] += e;
                    if (sv > mv[s]) { mv[s] = sv; mc[s] = cl; }
                    csum[c] += e;
                    if (sv > cv[c]) { cv[c] = sv; cim[c] = rl; }
                }
            }

    // ---- row direction: quad shfl reduce (lanes differing in lane&3) ----
    #pragma unroll
    for (int s = 0; s < 4; s++) {
        #pragma unroll
        for (int o = 1; o < 4; o <<= 1) {
            float of = __shfl_xor_sync(0xffffffffu, fsum[s], o);
            float ov = __shfl_xor_sync(0xffffffffu, mv[s],   o);
            int   oc = __shfl_xor_sync(0xffffffffu, mc[s],   o);
            fsum[s] += of;
            if (ov > mv[s] || (ov == mv[s] && oc < mc[s])) { mv[s] = ov; mc[s] = oc; }
        }
    }
    // combine wn halves via smem; wn=0 wins ties (smaller cols)
    if (wn == 1 && (lane & 3) == 0) {
        #pragma unroll
        for (int s = 0; s < 4; s++) {
            const int rl = wm * 32 + lq + s * 8;
            *(float*)(smraw + (sb - smem_u32(smraw)) + SM_RF + rl * 4) = fsum[s];
            *(float*)(smraw + (sb - smem_u32(smraw)) + SM_RV + rl * 4) = mv[s];
            *(int*)  (smraw + (sb - smem_u32(smraw)) + SM_RC + rl * 4) = mc[s];
        }
    }
    // ---- col direction: shfl reduce over lq (xor 4,8,16) ----
    #pragma unroll
    for (int c = 0; c < 16; c++) {
        #pragma unroll
        for (int o = 4; o < 32; o <<= 1) {
            float of = __shfl_xor_sync(0xffffffffu, csum[c], o);
            float ov = __shfl_xor_sync(0xffffffffu, cv[c],   o);
            int   oi = __shfl_xor_sync(0xffffffffu, cim[c],  o);
            csum[c] += of;
            if (ov > cv[c] || (ov == cv[c] && oi < cim[c])) { cv[c] = ov; cim[c] = oi; }
        }
    }
    __syncthreads();

    char* smb = smraw + (sb - smem_u32(smraw));
    if (wn == 0 && (lane & 3) == 0) {
        #pragma unroll
        for (int s = 0; s < 4; s++) {
            const int rl = wm * 32 + lq + s * 8;
            float f  = fsum[s] + *(float*)(smb + SM_RF + rl * 4);
            float ov = *(float*)(smb + SM_RV + rl * 4);
            int   oc = *(int*)  (smb + SM_RC + rl * 4);
            float bv = mv[s]; int bc = mc[s];
            if (ov > bv) { bv = ov; bc = oc; }
            const int row = bi * 128 + rl;
            g_pf [bj][row] = f;
            g_pmv[bj][row] = bv;
            g_pmc[bj][row] = bj * 128 + bc;
        }
    }
    if (lane < 4) {
        #pragma unroll
        for (int nf = 0; nf < 8; nf++)
            #pragma unroll
            for (int p = 0; p < 2; p++) {
                const int c  = nf * 2 + p;
                const int cl = wn * 64 + lane * 2 + nf * 8 + p;
                *(float*)(smb + SM_CF + (wm * 128 + cl) * 4) = csum[c];
                *(float*)(smb + SM_CV + (wm * 128 + cl) * 4) = cv[c];
                *(int*)  (smb + SM_CC + (wm * 128 + cl) * 4) = cim[c];
            }
    }
    __syncthreads();
    if (!isDiag && tid < 128) {
        const int cl = tid;
        float f = 0.0f, bv = -INFINITY; int br = 0;
        #pragma unroll
        for (int w = 0; w < 4; w++) {
            f += *(float*)(smb + SM_CF + (w * 128 + cl) * 4);
            float v = *(float*)(smb + SM_CV + (w * 128 + cl) * 4);
            int   r = *(int*)  (smb + SM_CC + (w * 128 + cl) * 4);
            if (v > bv || (v == bv && r < br)) { bv = v; br = r; }
        }
        const int row = bj * 128 + cl;
        g_pf [bi][row] = f;
        g_pmv[bi][row] = bv;
        g_pmc[bi][row] = bi * 128 + br;
    }
}

// ---------------- kernel 3a: per-row reduce over 64 slots ----------------
__global__ void finalizeA_kernel(const float* __restrict__ lt) {
    __shared__ float sl[256];
    __shared__ int   sc[256];
    const int tid = threadIdx.x;
    const int row = blockIdx.x * 256 + tid;
    const float invT = expf(-lt[0]);
    float fs = 0.0f, bv = -INFINITY;
    int bc = -1;
    #pragma unroll 8
    for (int o = 0; o < NBLK; o++) {
        fs += g_pf[o][row];
        float v = g_pmv[o][row];
        int   c = g_pmc[o][row];
        if (v > bv || (v == bv && c < bc)) { bv = v; bc = c; }
    }
    float lse = invT + logf(fs);
    sl[tid] = lse - g_tgt[row];
    sc[tid] = (bc == (row ^ 4096)) ? 1 : 0;
    __syncthreads();
    for (int s = 128; s > 0; s >>= 1) {
        if (tid < s) { sl[tid] += sl[tid + s]; sc[tid] += sc[tid + s]; }
        __syncthreads();
    }
    if (tid == 0) { g_redl[blockIdx.x] = sl[0]; g_redc[blockIdx.x] = sc[0]; }
}

// ---------------- kernel 3b: final scalar ----------------
__global__ void finalizeB_kernel(float* __restrict__ out) {
    const int tid = threadIdx.x;  // 32 threads
    float l = g_redl[tid];
    int   c = g_redc[tid];
    #pragma unroll
    for (int o = 16; o > 0; o >>= 1) {
        l += __shfl_xor_sync(0xffffffffu, l, o);
        c += __shfl_xor_sync(0xffffffffu, c, o);
    }
    if (tid == 0) {
        out[0] = l / (float)N2;
        out[1] = 0.5f * (float)c;
    }
}

extern "C" void kernel_launch(void* const* d_in, const int* in_sizes, int n_in,
                              void* d_out, int out_size) {
    const float* z1 = (const float*)d_in[0];
    const float* z2 = (const float*)d_in[1];
    const float* lt = (const float*)d_in[2];
    float* out = (float*)d_out;

    cudaFuncSetAttribute(sim_hmma_kernel,
                         cudaFuncAttributeMaxDynamicSharedMemorySize, SMEM_BYTES);

    normalize_kernel<<<N2 / 8, 256>>>(z1, z2);
    sim_hmma_kernel<<<NTILE, 256, SMEM_BYTES>>>(lt);
    finalizeA_kernel<<<32, 256>>>(lt);
    finalizeB_kernel<<<1, 32>>>(out);
}

// round 9
// speedup vs baseline: 10.3776x; 1.1718x over previous
#include <cuda_runtime.h>
#include <cuda_bf16.h>
#include <math.h>
#include <stdint.h>

// ---------------- problem constants ----------------
#define N_HALF 4096
#define N2     8192
#define Dm     256
#define EPSN   1e-8f
#define NBLK   64            // 8192 / 128 row blocks
#define NTILE  2080          // NBLK*(NBLK+1)/2 upper-tri tiles
#define GRID   148           // persistent CTAs

// ---------------- device scratch ----------------
__device__ __align__(16) __nv_bfloat16 gH[N2 * Dm];   // hi part, row-major
__device__ __align__(16) __nv_bfloat16 gL[N2 * Dm];   // lo part, row-major
// partials: slot o = "other" block; each (o,row) written exactly once
__device__ float g_pf [NBLK][N2];   // partial expsum (fixed shift C = 1/T)
__device__ float g_pmv[NBLK][N2];   // partial max sim
__device__ int   g_pmc[NBLK][N2];   // partial argmax col (global)
__device__ float g_tgt[N2];         // target logit per row
__device__ float g_redl[32];
__device__ int   g_redc[32];

// ---------------- PTX helpers (sm_80-era: compile under compute_103) ------
__device__ __forceinline__ uint32_t smem_u32(const void* p) {
    uint32_t a;
    asm("{ .reg .u64 t; cvta.to.shared.u64 t, %1; cvt.u32.u64 %0, t; }" : "=r"(a) : "l"(p));
    return a;
}
__device__ __forceinline__ void cp16(uint32_t sdst, const void* gsrc) {
    asm volatile("cp.async.cg.shared.global [%0], [%1], 16;" :: "r"(sdst), "l"(gsrc) : "memory");
}
__device__ __forceinline__ void cp_commit() {
    asm volatile("cp.async.commit_group;" ::: "memory");
}
__device__ __forceinline__ void cp_wait1() {
    asm volatile("cp.async.wait_group 1;" ::: "memory");
}
__device__ __forceinline__ void cp_wait0() {
    asm volatile("cp.async.wait_group 0;" ::: "memory");
}
__device__ __forceinline__ void ldm_x4(uint32_t* r, uint32_t addr) {
    asm volatile("ldmatrix.sync.aligned.m8n8.x4.shared.b16 {%0,%1,%2,%3}, [%4];"
        : "=r"(r[0]), "=r"(r[1]), "=r"(r[2]), "=r"(r[3]) : "r"(addr));
}
__device__ __forceinline__ void mma16816(float* d, const uint32_t* a, uint32_t b0, uint32_t b1) {
    asm volatile("mma.sync.aligned.m16n8k16.row.col.f32.bf16.bf16.f32 "
        "{%0,%1,%2,%3}, {%4,%5,%6,%7}, {%8,%9}, {%0,%1,%2,%3};"
        : "+f"(d[0]), "+f"(d[1]), "+f"(d[2]), "+f"(d[3])
        : "r"(a[0]), "r"(a[1]), "r"(a[2]), "r"(a[3]), "r"(b0), "r"(b1));
}

// smem map (offsets from 1024-aligned base)
#define SM_AH   0u          // 128 x 256 bf16 hi = 64KB (512B rows, swizzled)
#define SM_AL   65536u      // lo panel
#define SM_B    131072u     // 2 stages x 32KB (128 rows x 128 bf16, swizzled)
// dedicated epilogue reduction scratch (B stages hold live prefetch data)
#define SM_RF   196608u     // float[4][128] row expsum (by wn)
#define SM_RV   (SM_RF + 2048u)
#define SM_RC   (SM_RV + 2048u)
#define SM_CF   (SM_RC + 2048u)   // float[4][128] col expsum (by wm)
#define SM_CV   (SM_CF + 2048u)
#define SM_CC   (SM_CV + 2048u)
#define SMEM_BYTES (208896 + 1024 + 1024)   // 196608+12288 data + align slack

// ---------------- kernel 1: normalize + bf16 hi/lo split ----------------
__global__ void normalize_kernel(const float* __restrict__ z1,
                                 const float* __restrict__ z2) {
    int row  = blockIdx.x * 8 + (threadIdx.x >> 5);
    int lane = threadIdx.x & 31;
    const float* src = (row < N_HALF) ? (z1 + (size_t)row * Dm)
                                      : (z2 + (size_t)(row - N_HALF) * Dm);
    float4 a = *reinterpret_cast<const float4*>(src + lane * 8);
    float4 b = *reinterpret_cast<const float4*>(src + lane * 8 + 4);
    float s = a.x*a.x + a.y*a.y + a.z*a.z + a.w*a.w
            + b.x*b.x + b.y*b.y + b.z*b.z + b.w*b.w;
    #pragma unroll
    for (int off = 16; off > 0; off >>= 1)
        s += __shfl_xor_sync(0xffffffffu, s, off);
    float sc = 1.0f / fmaxf(sqrtf(s), EPSN);
    float v[8] = {a.x*sc, a.y*sc, a.z*sc, a.w*sc, b.x*sc, b.y*sc, b.z*sc, b.w*sc};
    union { __nv_bfloat16 h[8]; uint4 u; } H, L;
    #pragma unroll
    for (int i = 0; i < 8; i++) {
        H.h[i] = __float2bfloat16(v[i]);
        L.h[i] = __float2bfloat16(v[i] - __bfloat162float(H.h[i]));
    }
    *reinterpret_cast<uint4*>((uint8_t*)gH + (size_t)row * 512 + lane * 16) = H.u;
    *reinterpret_cast<uint4*>((uint8_t*)gL + (size_t)row * 512 + lane * 16) = L.u;
}

// ---------------- kernel 2: persistent symmetric HMMA split-GEMM ----------
// 148 persistent CTAs; CTA owns contiguous triangular-tile range (bi-major),
// A panel reloaded only on bi change. 16 warps: wm = wid&3 (32-row strip),
// wn = wid>>2 (32-col strip). K-chunks of 128; B double-buffered.
__global__ void __launch_bounds__(512, 1)
sim_hmma_kernel(const float* __restrict__ lt) {
    extern __shared__ char smraw[];
    uint32_t sb0 = smem_u32(smraw);
    uint32_t sb  = (sb0 + 1023u) & ~1023u;
    char* smb    = smraw + (sb - sb0);

    const int tid  = threadIdx.x;
    const int lane = tid & 31;
    const int wid  = tid >> 5;
    const int wm   = wid & 3;
    const int wn   = wid >> 2;

    const int cta = blockIdx.x;
    const int t0  = (cta * NTILE) / GRID;
    const int t1  = ((cta + 1) * NTILE) / GRID;

    const float invT = expf(-lt[0]);

    // decode starting (bi, bj): f(bi) = bi*(129-bi)/2
    int bi = 0;
    while ((bi + 1) * (128 - bi) / 2 <= t0) bi++;
    int bj = bi + (t0 - bi * (129 - bi) / 2);

    // load cursor (runs ahead of compute by up to 2 chunks)
    int ld_bj = bj, ld_q = 0;
    int ld_bi_dummy = bi;  (void)ld_bi_dummy;
    int lcnt = 0, ccnt = 0;
    const int totalc = (t1 - t0) * 4;
    int bi_loaded = -1;
    bool fullw = true;

    const uint32_t a_lo = (lane & 15) * 512u + (lane >> 4) * 16u;
    const uint32_t b_lo = (lane & 15) * 256u + (lane >> 4) * 16u;
    const uint32_t lxr  = (uint32_t)(lane & 7) << 4;
    const uint32_t AhB  = sb + SM_AH + wm * 16384u;
    const uint32_t AlB  = sb + SM_AL + wm * 16384u;

    auto issueB = [&]() {
        const uint8_t* g = (ld_q & 1) ? (const uint8_t*)gL : (const uint8_t*)gH;
        const int c = ld_q >> 1;
        const uint32_t st = (uint32_t)(lcnt & 1);
        int u = tid;
        #pragma unroll
        for (int i = 0; i < 4; i++, u += 512) {
            int rr = u >> 4, ku = u & 15;
            const uint8_t* gsrc = g + ((size_t)(ld_bj * 128 + rr)) * 512 + c * 256 + ku * 16;
            uint32_t sdst = (sb + SM_B + st * 32768u + (uint32_t)(rr * 256 + ku * 16))
                            ^ (uint32_t)((rr & 7) << 4);
            cp16(sdst, gsrc);
        }
        cp_commit();
        lcnt++;
        if (++ld_q == 4) {
            ld_q = 0;
            if (++ld_bj == NBLK) { ld_bi_dummy++; ld_bj = ld_bi_dummy; }
        }
    };

    auto loadA = [&](int bib) {
        int u = tid;
        #pragma unroll
        for (int i = 0; i < 16; i++, u += 512) {
            int panel = u >> 12, rr = (u >> 5) & 127, ku = u & 31;
            const uint8_t* g = panel ? (const uint8_t*)gL : (const uint8_t*)gH;
            const uint8_t* gsrc = g + ((size_t)(bib * 128 + rr)) * 512 + ku * 16;
            uint32_t sdst = (sb + panel * 65536u + (uint32_t)(rr * 512 + ku * 16))
                            ^ (uint32_t)((rr & 7) << 4);
            cp16(sdst, gsrc);
        }
        cp_commit();
    };

    for (int t = t0; t < t1; t++) {
        if (bi != bi_loaded) {
            loadA(bi);                 // A group inserted -> full drain before compute
            bi_loaded = bi;
            fullw = true;
        }
        while (lcnt < ccnt + 2 && lcnt < totalc) issueB();

        float acc[2][4][4];
        #pragma unroll
        for (int mf = 0; mf < 2; mf++)
            #pragma unroll
            for (int nb = 0; nb < 4; nb++)
                #pragma unroll
                for (int v = 0; v < 4; v++) acc[mf][nb][v] = 0.0f;

        #pragma unroll
        for (int q = 0; q < 4; q++) {
            if (fullw) { cp_wait0(); fullw = false; } else { cp_wait1(); }
            __syncthreads();

            const uint32_t st = (uint32_t)(ccnt & 1);
            const int kb = (q >> 1) * 128;
            const bool dual = ((q & 1) == 0);   // Bh chunk -> hh + lh terms
            const uint32_t Bst = sb + SM_B + st * 32768u + wn * 8192u;

            #pragma unroll
            for (int kk = 0; kk < 128; kk += 16) {
                uint32_t bfr[2][4];
                ldm_x4(bfr[0], (Bst + 0u    + kk * 2u + b_lo) ^ lxr);
                ldm_x4(bfr[1], (Bst + 4096u + kk * 2u + b_lo) ^ lxr);
                uint32_t af[2][4];
                ldm_x4(af[0], (AhB + 0u    + (kb + kk) * 2u + a_lo) ^ lxr);
                ldm_x4(af[1], (AhB + 8192u + (kb + kk) * 2u + a_lo) ^ lxr);
                #pragma unroll
                for (int mf = 0; mf < 2; mf++)
                    #pragma unroll
                    for (int nb = 0; nb < 2; nb++) {
                        mma16816(acc[mf][nb*2  ], af[mf], bfr[nb][0], bfr[nb][2]);
                        mma16816(acc[mf][nb*2+1], af[mf], bfr[nb][1], bfr[nb][3]);
                    }
                if (dual) {
                    uint32_t al[2][4];
                    ldm_x4(al[0], (AlB + 0u    + (kb + kk) * 2u + a_lo) ^ lxr);
                    ldm_x4(al[1], (AlB + 8192u + (kb + kk) * 2u + a_lo) ^ lxr);
                    #pragma unroll
                    for (int mf = 0; mf < 2; mf++)
                        #pragma unroll
                        for (int nb = 0; nb < 2; nb++) {
                            mma16816(acc[mf][nb*2  ], al[mf], bfr[nb][0], bfr[nb][2]);
                            mma16816(acc[mf][nb*2+1], al[mf], bfr[nb][1], bfr[nb][3]);
                        }
                }
            }
            __syncthreads();
            ccnt++;
            if (lcnt < totalc) issueB();
        }

        // ============== epilogue: dual-direction reduction ==============
        const int  lq     = lane >> 2;
        const bool isDiag = (bi == bj);
        const bool isTgt  = (bj == bi + 32);

        float fsum[4], mv[4];  int mc[4];     // row direction (4 row slots)
        float csum[8], cv[8];  int cim[8];    // col direction (8 col slots)
        #pragma unroll
        for (int s = 0; s < 4; s++) { fsum[s] = 0.0f; mv[s] = -INFINITY; mc[s] = 0; }
        #pragma unroll
        for (int c = 0; c < 8; c++) { csum[c] = 0.0f; cv[c] = -INFINITY; cim[c] = 0; }

        #pragma unroll
        for (int mf = 0; mf < 2; mf++)
            #pragma unroll
            for (int nb = 0; nb < 4; nb++)
                #pragma unroll
                for (int v = 0; v < 4; v++) {
                    const int rl = wm * 32 + mf * 16 + lq + (v >> 1) * 8;
                    const int cl = wn * 32 + (lane & 3) * 2 + nb * 8 + (v & 1);
                    const float sv = acc[mf][nb][v];
                    const float e  = __expf((sv - 1.0f) * invT);
                    const bool same = (rl == cl);
                    if (isTgt && same) {
                        const float tv = sv * invT;
                        g_tgt[bi * 128 + rl]        = tv;
                        g_tgt[bi * 128 + rl + 4096] = tv;
                    }
                    if (!(isDiag && same)) {
                        const int s = mf * 2 + (v >> 1);
                        const int c = nb * 2 + (v & 1);
                        fsum[s] += e;
                        if (sv > mv[s]) { mv[s] = sv; mc[s] = cl; }
                        csum[c] += e;
                        if (sv > cv[c]) { cv[c] = sv; cim[c] = rl; }
                    }
                }

        // row dir: quad shfl reduce (over lane&3)
        #pragma unroll
        for (int s = 0; s < 4; s++) {
            #pragma unroll
            for (int o = 1; o < 4; o <<= 1) {
                float of = __shfl_xor_sync(0xffffffffu, fsum[s], o);
                float ov = __shfl_xor_sync(0xffffffffu, mv[s],   o);
                int   oc = __shfl_xor_sync(0xffffffffu, mc[s],   o);
                fsum[s] += of;
                if (ov > mv[s] || (ov == mv[s] && oc < mc[s])) { mv[s] = ov; mc[s] = oc; }
            }
        }
        if ((lane & 3) == 0) {
            #pragma unroll
            for (int s = 0; s < 4; s++) {
                const int rl = wm * 32 + s * 8 + lq;
                *(float*)(smb + SM_RF + (wn * 128 + rl) * 4) = fsum[s];
                *(float*)(smb + SM_RV + (wn * 128 + rl) * 4) = mv[s];
                *(int*)  (smb + SM_RC + (wn * 128 + rl) * 4) = mc[s];
            }
        }
        // col dir: shfl reduce over lq (xor 4,8,16)
        #pragma unroll
        for (int c = 0; c < 8; c++) {
            #pragma unroll
            for (int o = 4; o < 32; o <<= 1) {
                float of = __shfl_xor_sync(0xffffffffu, csum[c], o);
                float ov = __shfl_xor_sync(0xffffffffu, cv[c],   o);
                int   oi = __shfl_xor_sync(0xffffffffu, cim[c],  o);
                csum[c] += of;
                if (ov > cv[c] || (ov == cv[c] && oi < cim[c])) { cv[c] = ov; cim[c] = oi; }
            }
        }
        if (lane < 4) {
            #pragma unroll
            for (int c = 0; c < 8; c++) {
                const int cl = wn * 32 + lane * 2 + (c >> 1) * 8 + (c & 1);
                *(float*)(smb + SM_CF + (wm * 128 + cl) * 4) = csum[c];
                *(float*)(smb + SM_CV + (wm * 128 + cl) * 4) = cv[c];
                *(int*)  (smb + SM_CC + (wm * 128 + cl) * 4) = cim[c];
            }
        }
        __syncthreads();

        if (tid < 128) {
            {   // row direction -> rows of block bi, slot bj
                const int rl = tid;
                float f = 0.0f, bv = -INFINITY; int bc = 0;
                #pragma unroll
                for (int w = 0; w < 4; w++) {
                    f += *(float*)(smb + SM_RF + (w * 128 + rl) * 4);
                    float v2 = *(float*)(smb + SM_RV + (w * 128 + rl) * 4);
                    int   c2 = *(int*)  (smb + SM_RC + (w * 128 + rl) * 4);
                    if (v2 > bv) { bv = v2; bc = c2; }
                }
                const int row = bi * 128 + rl;
                g_pf [bj][row] = f;
                g_pmv[bj][row] = bv;
                g_pmc[bj][row] = bj * 128 + bc;
            }
            if (!isDiag) {   // col direction -> rows of block bj, slot bi
                const int cl = tid;
                float f = 0.0f, bv = -INFINITY; int br = 0;
                #pragma unroll
                for (int w = 0; w < 4; w++) {
                    f += *(float*)(smb + SM_CF + (w * 128 + cl) * 4);
                    float v2 = *(float*)(smb + SM_CV + (w * 128 + cl) * 4);
                    int   r2 = *(int*)  (smb + SM_CC + (w * 128 + cl) * 4);
                    if (v2 > bv) { bv = v2; br = r2; }
                }
                const int row = bj * 128 + cl;
                g_pf [bi][row] = f;
                g_pmv[bi][row] = bv;
                g_pmc[bi][row] = bi * 128 + br;
            }
        }

        if (++bj == NBLK) { bi++; bj = bi; }
    }
}

// ---------------- kernel 3a: per-row reduce over 64 slots ----------------
__global__ void finalizeA_kernel(const float* __restrict__ lt) {
    __shared__ float sl[256];
    __shared__ int   sc[256];
    const int tid = threadIdx.x;
    const int row = blockIdx.x * 256 + tid;
    const float invT = expf(-lt[0]);
    float fs = 0.0f, bv = -INFINITY;
    int bc = -1;
    #pragma unroll 8
    for (int o = 0; o < NBLK; o++) {
        fs += g_pf[o][row];
        float v = g_pmv[o][row];
        int   c = g_pmc[o][row];
        if (v > bv || (v == bv && c < bc)) { bv = v; bc = c; }
    }
    float lse = invT + logf(fs);
    sl[tid] = lse - g_tgt[row];
    sc[tid] = (bc == (row ^ 4096)) ? 1 : 0;
    __syncthreads();
    for (int s = 128; s > 0; s >>= 1) {
        if (tid < s) { sl[tid] += sl[tid + s]; sc[tid] += sc[tid + s]; }
        __syncthreads();
    }
    if (tid == 0) { g_redl[blockIdx.x] = sl[0]; g_redc[blockIdx.x] = sc[0]; }
}

// ---------------- kernel 3b: final scalar ----------------
__global__ void finalizeB_kernel(float* __restrict__ out) {
    const int tid = threadIdx.x;  // 32 threads
    float l = g_redl[tid];
    int   c = g_redc[tid];
    #pragma unroll
    for (int o = 16; o > 0; o >>= 1) {
        l += __shfl_xor_sync(0xffffffffu, l, o);
        c += __shfl_xor_sync(0xffffffffu, c, o);
    }
    if (tid == 0) {
        out[0] = l / (float)N2;
        out[1] = 0.5f * (float)c;
    }
}

extern "C" void kernel_launch(void* const* d_in, const int* in_sizes, int n_in,
                              void* d_out, int out_size) {
    const float* z1 = (const float*)d_in[0];
    const float* z2 = (const float*)d_in[1];
    const float* lt = (const float*)d_in[2];
    float* out = (float*)d_out;

    cudaFuncSetAttribute(sim_hmma_kernel,
                         cudaFuncAttributeMaxDynamicSharedMemorySize, SMEM_BYTES);

    normalize_kernel<<<N2 / 8, 256>>>(z1, z2);
    sim_hmma_kernel<<<GRID, 512, SMEM_BYTES>>>(lt);
    finalizeA_kernel<<<32, 256>>>(lt);
    finalizeB_kernel<<<1, 32>>>(out);
}